// round 17
// baseline (speedup 1.0000x reference)
#include <cuda_runtime.h>

// RSI fused single pass, v17 = v8 window engine at ITEMS=32. out[c] =
// g/(g+l) over 13-wide window of +/- relative deltas (0 if no losses).
//
// R16 showed L1 is no longer binding (61% with no speedup): the cost is
// instructions/output at issue ~74%. ITEMS=32 amortizes warm-up (1.75 ->
// 1.375 window iters/output), halves exchange + halo cost per output.
// One warp = 1024 outputs, one block = one full row.
// Layouts (bank-verified): p-exchange stride-12 (publish p[0..11] only --
// exactly what the neighbor reads); ov quad-skew Q(q)=q+(q>>3), writer
// (lane+qi)%8 and reader (36m+lane)%32 both conflict-free.
// Keeps: .cs hints (v15), S-slide + exact L-prefix (v8), guarded lane-31
// LDG (no shuffle chains, R7/R12), no launch_bounds cap (R9).

#define NROWS  2048
#define NCOLS  8192
#define TPB    256
#define ITEMS  32
#define WTILE  1024              // outputs per warp
#define TILE   8192              // outputs per block = full row
#define MAXW   64
#define SLOTP  12                // p floats per lane slot (12 shared values)
#define PREG   400               // 12*33 = 396 -> pad to 16B multiple
#define OREG   1152              // 4*Q(255)+4 = 1148 -> pad

__global__ __launch_bounds__(TPB) void rsi_v17(
    const float* __restrict__ in,
    float* __restrict__ out,
    int out_cols)
{
    __shared__ __align__(16) float s_p[8 * PREG];
    __shared__ __align__(16) float s_o[8 * OREG];

    const int tid   = threadIdx.x;
    const int lane  = tid & 31;
    const int wrp   = tid >> 5;
    const int row   = blockIdx.y;
    const int wbase = wrp * WTILE;                       // warp's first column
    const float* rin = in + (size_t)row * NCOLS;
    float* pw = s_p + wrp * PREG;
    float* ow = s_o + wrp * OREG;
    float* myp  = pw + SLOTP * lane;
    float* myov = ow + 36 * lane;                        // quads 8*lane.. contiguous

    const bool edge = (wbase + WTILE) > out_cols;        // last warp of the row

    // ---- load own 32 inputs (g0+31 <= 8191 always) ----
    const int g0 = wbase + ITEMS * lane;
    float4 xq[8];
    #pragma unroll
    for (int q = 0; q < 8; ++q)
        xq[q] = __ldcs((const float4*)(rin + g0 + 4 * q));

    // x[g0+32]: neighbor's first x via shuffle; lane 31 loads (guarded)
    float x32 = __shfl_down_sync(0xffffffffu, xq[0].x, 1);
    if (lane == 31)
        x32 = (g0 + 32 < NCOLS) ? rin[g0 + 32] : 0.0f;

    // halo x: lanes 0..12 load x[wbase+1024+lane] (zero past row end)
    float xe = 0.0f;
    if (lane < 13) {
        const int ge = wbase + WTILE + lane;
        xe = (ge < NCOLS) ? rin[ge] : 0.0f;
    }
    const float xen = __shfl_down_sync(0xffffffffu, xe, 1);

    // ---- own 32 p-values ----
    float xs[33];
    #pragma unroll
    for (int q = 0; q < 8; ++q) {
        xs[4 * q]     = xq[q].x;
        xs[4 * q + 1] = xq[q].y;
        xs[4 * q + 2] = xq[q].z;
        xs[4 * q + 3] = xq[q].w;
    }
    xs[32] = x32;
    float p[ITEMS];
    #pragma unroll
    for (int c = 0; c < ITEMS; ++c) {
        const float prev = xs[c];
        p[c] = (prev != 0.0f) ? __fdividef(xs[c + 1] - prev, prev) : 0.0f;
    }

    // ---- publish p[0..11] (all the neighbor reads), stride-12 ----
    *(float4*)(myp)     = make_float4(p[0], p[1], p[2],  p[3]);
    *(float4*)(myp + 4) = make_float4(p[4], p[5], p[6],  p[7]);
    *(float4*)(myp + 8) = make_float4(p[8], p[9], p[10], p[11]);
    if (lane < 12) {                                     // halo p -> slot 32
        const float pe = (xe != 0.0f) ? __fdividef(xen - xe, xe) : 0.0f;
        pw[SLOTP * 32 + lane] = pe;
    }
    __syncwarp();

    // ---- fetch 12 neighbor p-values (lane 31 hits halo slot 32) ----
    const float* nbp = pw + SLOTP * (lane + 1);
    const float4 n0 = *(const float4*)(nbp);
    const float4 n1 = *(const float4*)(nbp + 4);
    const float4 n2 = *(const float4*)(nbp + 8);
    const float n[12] = {n0.x, n0.y, n0.z, n0.w, n1.x, n1.y, n1.z, n1.w,
                         n2.x, n2.y, n2.z, n2.w};

    // ---- 32 sliding 13-windows, one continuous pass.
    // L: prefix + snapshot (bitwise-exact l==0). S: sliding signed window.
    float S = 0.0f, L = 0.0f;
    float ql[ITEMS], ov4[4];
    #pragma unroll
    for (int j = 0; j < ITEMS + 12; ++j) {               // 44 iters
        if (j < ITEMS) ql[j] = L;
        const float vj = (j < ITEMS) ? p[j] : n[j - ITEMS];
        L += fmaxf(-vj, 0.0f);
        S += vj;
        if (j >= 13) S -= p[j - 13];                     // j-13 <= 30: own p
        if (j >= 12) {
            const int k = j - 12;
            const float l = L - ql[k];                   // exact over window
            const float t = S + l;                       // g = S + l
            ov4[k & 3] = (l != 0.0f) ? __fdividef(t, t + l) : 0.0f;
            if ((k & 3) == 3)                            // quad qi=(k-3)/4 at +k-3
                *(float4*)(myov + (k - 3)) =
                    make_float4(ov4[0], ov4[1], ov4[2], ov4[3]);
        }
    }
    __syncwarp();

    // ---- coalesced streaming stores, conflict-free quad-skew reads ----
    float* rout = out + (size_t)row * out_cols;
    if (!edge) {
        #pragma unroll
        for (int m = 0; m < ITEMS; ++m) {
            const int o = lane + 32 * m;
            __stcs(rout + wbase + o, ow[4 * (9 * m + (lane >> 2)) + (lane & 3)]);
        }
    } else {
        const int nvalid = out_cols - wbase;
        #pragma unroll
        for (int m = 0; m < ITEMS; ++m) {
            const int o = lane + 32 * m;
            if (o < nvalid)
                __stcs(rout + wbase + o, ow[4 * (9 * m + (lane >> 2)) + (lane & 3)]);
        }
    }
}

// ---- Generic fallback for unexpected window sizes ----
__global__ __launch_bounds__(256) void rsi_generic(
    const float* __restrict__ in,
    float* __restrict__ out,
    int out_cols, int w)
{
    __shared__ float s_in[256 + MAXW + 1];
    __shared__ float s_g [256 + MAXW];
    __shared__ float s_l [256 + MAXW];

    const int row  = blockIdx.y;
    const int base = blockIdx.x * 256;
    const float* rin = in + (size_t)row * NCOLS;

    const int need_in = 256 + w + 1;
    for (int i = threadIdx.x; i < need_in; i += 256) {
        const int col = base + i;
        s_in[i] = (col < NCOLS) ? rin[col] : 0.0f;
    }
    __syncthreads();

    const int need_p = 256 + w;
    for (int i = threadIdx.x; i < need_p; i += 256) {
        const float prev = s_in[i];
        const float cur  = s_in[i + 1];
        const float p = (prev != 0.0f) ? (cur - prev) / prev : 0.0f;
        s_g[i] = fmaxf(p, 0.0f);
        s_l[i] = fmaxf(-p, 0.0f);
    }
    __syncthreads();

    const int c = base + threadIdx.x;
    if (c < out_cols) {
        float g = 0.0f, l = 0.0f;
        for (int j = 0; j < w; ++j) {
            g += s_g[threadIdx.x + j];
            l += s_l[threadIdx.x + j];
        }
        out[(size_t)row * out_cols + c] = (l != 0.0f) ? g / (g + l) : 0.0f;
    }
}

extern "C" void kernel_launch(void* const* d_in, const int* in_sizes, int n_in,
                              void* d_out, int out_size)
{
    const float* in  = (const float*)d_in[0];
    float*       out = (float*)d_out;

    const int out_cols = out_size / NROWS;   // NCOLS - (window_size - 1)
    int w = NCOLS - out_cols;

    if (w == 13) {
        dim3 grid(1, NROWS);                 // one block per row
        rsi_v17<<<grid, TPB>>>(in, out, out_cols);
    } else {
        if (w < 1)    w = 1;
        if (w > MAXW) w = MAXW;
        dim3 grid((out_cols + 255) / 256, NROWS);
        rsi_generic<<<grid, 256>>>(in, out, out_cols, w);
    }
}